// round 14
// baseline (speedup 1.0000x reference)
#include <cuda_runtime.h>
#include <cuda_bf16.h>

// ---------------------------------------------------------------------------
// 9-wire statevector simulator. One warp per batch item, 16 complex amps/lane.
// SoA f32x2 packing: u64 re[8]/im[8] hold (component of amp q, amp q+8),
// pairing along reg bit 3 (= wire 5).
//
// R12: real-M0 specialized paths for reg-controlled entangle gates (halved
// FMA in the control=0 branch); 96-thread blocks for 27 warps/SM.
//
// Amplitude index idx[8:0]: wire w <-> bit (8-w).
//   wires 0..4 -> lane bits 4..0 (shuffles)
//   wire  5    -> f32x2 packed half
//   wires 6..8 -> reg bits 2..0 of q
// ---------------------------------------------------------------------------

using u64 = unsigned long long;

#define N_SLOTS   101                  // 99 fused gates + 2 standalone Rots
#define SLOT_U64  24                   // 192 bytes per gate slot
#define RY0_F     (N_SLOTS * SLOT_U64 * 2)   // float index of (ca,sa)

template<int V> struct IC { static constexpr int value = V; };
template<int N, typename F>
__device__ __forceinline__ void static_for(F&& f) {
    if constexpr (N > 0) { static_for<N - 1>(f); f(IC<N - 1>{}); }
}

// ------------------------- packed f32x2 helpers ----------------------------
__device__ __forceinline__ u64 pk2(float lo, float hi) {
    u64 r;
    asm("mov.b64 %0, {%1, %2};" : "=l"(r)
        : "r"(__float_as_uint(lo)), "r"(__float_as_uint(hi)));
    return r;
}
__device__ __forceinline__ void upk2(u64 a, float& lo, float& hi) {
    unsigned l_, h_;
    asm("mov.b64 {%0, %1}, %2;" : "=r"(l_), "=r"(h_) : "l"(a));
    lo = __uint_as_float(l_); hi = __uint_as_float(h_);
}
__device__ __forceinline__ u64 swp(u64 a) {
    float x, y; upk2(a, x, y); return pk2(y, x);
}
__device__ __forceinline__ u64 ffma2(u64 a, u64 b, u64 c) {
    u64 d; asm("fma.rn.f32x2 %0, %1, %2, %3;" : "=l"(d) : "l"(a), "l"(b), "l"(c));
    return d;
}
__device__ __forceinline__ u64 fmul2(u64 a, u64 b) {
    u64 d; asm("mul.rn.f32x2 %0, %1, %2;" : "=l"(d) : "l"(a), "l"(b));
    return d;
}
__device__ __forceinline__ u64 shx(u64 v, int m) { return __shfl_xor_sync(0xffffffffu, v, m); }

// --------------------- coefficient bundles (loaded from smem) --------------
// AB record (6 u64): Ar,Ai,nAi,Br,Bi,nBi  — out = A*self + B*partner
struct CoefAB { u64 Ar, Ai, nAi, Br, Bi, nBi; };
__device__ __forceinline__ CoefAB ldAB(const u64* r) {
    return { r[0], r[1], r[2], r[3], r[4], r[5] };
}
__device__ __forceinline__ void apply_AB(u64& re, u64& im, u64 pre, u64 pim, const CoefAB& c) {
    u64 nre = ffma2(c.Br, pre, ffma2(c.nBi, pim, ffma2(c.nAi, im, fmul2(c.Ar, re))));
    u64 nim = ffma2(c.Bi, pre, ffma2(c.Br, pim, ffma2(c.Ai, re, fmul2(c.Ar, im))));
    re = nre; im = nim;
}
// PQ (target = packed wire 5): same six-slot record
__device__ __forceinline__ void apply_PQ(u64& re, u64& im, const CoefAB& c) {
    u64 sre = swp(re), sim = swp(im);
    u64 nre = ffma2(c.Br, sre, ffma2(c.nBi, sim, ffma2(c.nAi, im, fmul2(c.Ar, re))));
    u64 nim = ffma2(c.Bi, sre, ffma2(c.Br, sim, ffma2(c.Ai, re, fmul2(c.Ar, im))));
    re = nre; im = nim;
}
// Full 2x2 record (12 u64)
struct CoefM { u64 r00, i00, n00, r01, i01, n01, r10, i10, n10, r11, i11, n11; };
__device__ __forceinline__ CoefM ldM(const u64* r) {
    return { r[0], r[1], r[2], r[3], r[4], r[5], r[6], r[7], r[8], r[9], r[10], r[11] };
}
__device__ __forceinline__ void apply_pair(u64& req, u64& imq, u64& rep, u64& imp, const CoefM& c) {
    u64 nreq = ffma2(c.r01, rep, ffma2(c.n01, imp, ffma2(c.n00, imq, fmul2(c.r00, req))));
    u64 nimq = ffma2(c.i01, rep, ffma2(c.r01, imp, ffma2(c.i00, req, fmul2(c.r00, imq))));
    u64 nrep = ffma2(c.r11, rep, ffma2(c.n11, imp, ffma2(c.n10, imq, fmul2(c.r10, req))));
    u64 nimp = ffma2(c.i11, rep, ffma2(c.r11, imp, ffma2(c.i10, req, fmul2(c.r10, imq))));
    req = nreq; imq = nimq; rep = nrep; imp = nimp;
}

// ------------------------------ gate ---------------------------------------
// MODE 0: generic layouts (as R11).
// MODE 1: C in {6,7}, T=C+1 (both reg), M0 REAL: [4 u64 realM0][12 u64 M1]
// MODE 2: C=8 (reg), T=0 (lane), M0 REAL: per tb (stride 8 u64):
//         [Ar,Br real: 2 u64][c1 AB: 6 u64]
template<int C, int T, int MODE = 0>
__device__ __forceinline__ void gate(u64 (&re)[8], u64 (&im)[8], const u64* g, int lane) {
    if constexpr (T < 5) {
        constexpr int LMT = 1 << (4 - T);
        int tb = (lane >> (4 - T)) & 1;
        if constexpr (C < 5) {
            int cb = (lane >> (4 - C)) & 1;
            CoefAB c = ldAB(g + (cb * 2 + tb) * 6);
#pragma unroll
            for (int q = 0; q < 8; q++) {
                u64 pre = shx(re[q], LMT), pim = shx(im[q], LMT);
                apply_AB(re[q], im[q], pre, pim, c);
            }
        } else if constexpr (MODE == 2) {   // C==8, real M0
            const u64* r = g + tb * 8;
            u64 A0 = r[0], B0 = r[1];
            CoefAB c1 = ldAB(r + 2);
#pragma unroll
            for (int q = 0; q < 8; q++) {
                u64 pre = shx(re[q], LMT), pim = shx(im[q], LMT);
                if (q & 1) {
                    apply_AB(re[q], im[q], pre, pim, c1);
                } else {
                    re[q] = ffma2(B0, pre, fmul2(A0, re[q]));
                    im[q] = ffma2(B0, pim, fmul2(A0, im[q]));
                }
            }
        } else {   // generic C >= 6
            constexpr int MC = 1 << (8 - C);
            const u64* r = g + tb * 12;
            CoefAB c0 = ldAB(r), c1 = ldAB(r + 6);
#pragma unroll
            for (int q = 0; q < 8; q++) {
                u64 pre = shx(re[q], LMT), pim = shx(im[q], LMT);
                apply_AB(re[q], im[q], pre, pim, (q & MC) ? c1 : c0);
            }
        }
    } else if constexpr (T == 5) {      // control always a lane wire here
        int cb = (lane >> (4 - C)) & 1;
        CoefAB c = ldAB(g + cb * 6);
#pragma unroll
        for (int q = 0; q < 8; q++) apply_PQ(re[q], im[q], c);
    } else {
        constexpr int MT = 1 << (8 - T);
        if constexpr (C < 5) {
            int cb = (lane >> (4 - C)) & 1;
            CoefM c = ldM(g + cb * 12);
#pragma unroll
            for (int q = 0; q < 8; q++) if (!(q & MT))
                apply_pair(re[q], im[q], re[q | MT], im[q | MT], c);
        } else if constexpr (C == 5) {
            CoefM c = ldM(g);
#pragma unroll
            for (int q = 0; q < 8; q++) if (!(q & MT))
                apply_pair(re[q], im[q], re[q | MT], im[q | MT], c);
        } else if constexpr (MODE == 1) {   // both reg, real M0
            constexpr int MC = 1 << (8 - C);
            {
                u64 q00 = g[0], q01 = g[1], q10 = g[2], q11 = g[3];
#pragma unroll
                for (int q = 0; q < 8; q++) if (!(q & MT) && !(q & MC)) {
                    u64 ar = re[q], br = re[q | MT], ai = im[q], bi = im[q | MT];
                    re[q]      = ffma2(q01, br, fmul2(q00, ar));
                    im[q]      = ffma2(q01, bi, fmul2(q00, ai));
                    re[q | MT] = ffma2(q11, br, fmul2(q10, ar));
                    im[q | MT] = ffma2(q11, bi, fmul2(q10, ai));
                }
            }
            {
                CoefM c = ldM(g + 4);
#pragma unroll
                for (int q = 0; q < 8; q++) if (!(q & MT) && (q & MC))
                    apply_pair(re[q], im[q], re[q | MT], im[q | MT], c);
            }
        } else {
            constexpr int MC = 1 << (8 - C);
            {
                CoefM c = ldM(g);
#pragma unroll
                for (int q = 0; q < 8; q++) if (!(q & MT) && !(q & MC))
                    apply_pair(re[q], im[q], re[q | MT], im[q | MT], c);
            }
            {
                CoefM c = ldM(g + 12);
#pragma unroll
                for (int q = 0; q < 8; q++) if (!(q & MT) && (q & MC))
                    apply_pair(re[q], im[q], re[q | MT], im[q | MT], c);
            }
        }
    }
}

// Standalone 1q on lane wire W: 2 AB records indexed by tbit
template<int W>
__device__ __forceinline__ void g_1q(u64 (&re)[8], u64 (&im)[8], const u64* g, int lane) {
    constexpr int LMT = 1 << (4 - W);
    int tb = (lane >> (4 - W)) & 1;
    CoefAB c = ldAB(g + tb * 6);
#pragma unroll
    for (int q = 0; q < 8; q++) {
        u64 pre = shx(re[q], LMT), pim = shx(im[q], LMT);
        apply_AB(re[q], im[q], pre, pim, c);
    }
}

// ------------------------- prep: complex 2x2 algebra -----------------------
struct cpx { float r, i; };
__device__ __forceinline__ cpx cmulh(cpx x, cpx y) {
    return { x.r * y.r - x.i * y.i, x.r * y.i + x.i * y.r };
}
__device__ __forceinline__ cpx caddh(cpx x, cpx y) { return { x.r + y.r, x.i + y.i }; }
struct mat2 { cpx m00, m01, m10, m11; };
__device__ mat2 mmul(mat2 A, mat2 B) {
    return { caddh(cmulh(A.m00, B.m00), cmulh(A.m01, B.m10)),
             caddh(cmulh(A.m00, B.m01), cmulh(A.m01, B.m11)),
             caddh(cmulh(A.m10, B.m00), cmulh(A.m11, B.m10)),
             caddh(cmulh(A.m10, B.m01), cmulh(A.m11, B.m11)) };
}
__device__ mat2 mI() { return { {1,0},{0,0},{0,0},{1,0} }; }
__device__ mat2 mX() { return { {0,0},{1,0},{1,0},{0,0} }; }
__device__ mat2 mRY(float t) {
    float c, s; sincosf(0.5f * t, &s, &c);
    return { {c,0},{-s,0},{s,0},{c,0} };
}
__device__ mat2 mRot(const float* w) {
    float phi = w[0], th = w[1], om = w[2];
    float ct, st; sincosf(0.5f * th, &st, &ct);
    float ca, sa; sincosf(0.5f * (phi + om), &sa, &ca);
    float cb, sb; sincosf(0.5f * (phi - om), &sb, &cb);
    return { { ct * ca, -ct * sa }, { -st * cb, -st * sb },
             { st * cb, -st * sb }, { ct * ca,  ct * sa } };
}
__device__ mat2 mK0(float pb) {
    float cb, sb; sincosf(0.5f * pb, &sb, &cb);
    return { {sb,0},{cb,0},{cb,0},{-sb,0} };
}
__device__ mat2 mK1(float pb, float pz, float px) {
    float cb, sb; sincosf(0.5f * pb, &sb, &cb);
    float cz, sz; sincosf(0.5f * pz, &sz, &cz);
    float cx, sx; sincosf(0.5f * px, &sx, &cx);
    float d00r =  cz * cb, d00i =  sz * cb;
    float d01r = -cz * sb, d01i = -sz * sb;
    float d10r =  cz * sb, d10i = -sz * sb;
    float d11r =  cz * cb, d11i = -sz * cb;
    mat2 W;
    W.m00 = {  cx * d00r + sx * d10i,  cx * d00i - sx * d10r };
    W.m01 = {  cx * d01r + sx * d11i,  cx * d01i - sx * d11r };
    W.m10 = {  sx * d00i + cx * d10r, -sx * d00r + cx * d10i };
    W.m11 = {  sx * d01i + cx * d11r, -sx * d01r + cx * d11i };
    return W;
}

// ---- record writers (float offsets) ----
__device__ __forceinline__ cpx selA(const mat2& M, int tb) { return tb ? M.m11 : M.m00; }
__device__ __forceinline__ cpx selB(const mat2& M, int tb) { return tb ? M.m10 : M.m01; }
__device__ void wAB(float* o, cpx A, cpx B) {
    o[0] = A.r; o[1] = A.r; o[2] = A.i; o[3] = A.i; o[4] = -A.i; o[5] = -A.i;
    o[6] = B.r; o[7] = B.r; o[8] = B.i; o[9] = B.i; o[10] = -B.i; o[11] = -B.i;
}
__device__ void wM(float* o, mat2 M) {
    cpx v[4] = { M.m00, M.m01, M.m10, M.m11 };
    for (int k = 0; k < 4; k++) {
        o[k*6+0] = v[k].r; o[k*6+1] = v[k].r;
        o[k*6+2] = v[k].i; o[k*6+3] = v[k].i;
        o[k*6+4] = -v[k].i; o[k*6+5] = -v[k].i;
    }
}
__device__ void wMmix(float* o, mat2 A, mat2 B) {   // halves (A=ctrl0, B=ctrl1) on wire5
    cpx va[4] = { A.m00, A.m01, A.m10, A.m11 };
    cpx vb[4] = { B.m00, B.m01, B.m10, B.m11 };
    for (int k = 0; k < 4; k++) {
        o[k*6+0] = va[k].r; o[k*6+1] = vb[k].r;
        o[k*6+2] = va[k].i; o[k*6+3] = vb[k].i;
        o[k*6+4] = -va[k].i; o[k*6+5] = -vb[k].i;
    }
}
__device__ void wPQ(float* o, mat2 M) {   // P=(m00,m11) diag halves, Q=(m01,m10)
    o[0] = M.m00.r; o[1] = M.m11.r; o[2] = M.m00.i; o[3] = M.m11.i;
    o[4] = -M.m00.i; o[5] = -M.m11.i;
    o[6] = M.m01.r; o[7] = M.m10.r; o[8] = M.m01.i; o[9] = M.m10.i;
    o[10] = -M.m01.i; o[11] = -M.m10.i;
}

// expand gate (C,T) with blocks M0,M1 into slot table (generic layouts)
__device__ void expand(float* o, int C, int T, mat2 M0, mat2 M1) {
    if (T < 5 && C < 5) {
        for (int cb = 0; cb < 2; cb++) for (int tb = 0; tb < 2; tb++) {
            mat2& M = cb ? M1 : M0;
            wAB(o + (cb * 2 + tb) * 12, selA(M, tb), selB(M, tb));
        }
    } else if (T < 5) {                    // C >= 6
        for (int tb = 0; tb < 2; tb++) {
            wAB(o + tb * 24,      selA(M0, tb), selB(M0, tb));
            wAB(o + tb * 24 + 12, selA(M1, tb), selB(M1, tb));
        }
    } else if (T == 5) {                   // C < 5 always
        wPQ(o, M0); wPQ(o + 12, M1);
    } else if (C == 5) {
        wMmix(o, M0, M1);
    } else {                               // [M0 | M1] records
        wM(o, M0); wM(o + 24, M1);
    }
}

// in-block prep: fusion logic + per-lane expansion (incl. real-M0 layouts)
__device__ void prep_slot(float* fs, const float* params,
                          const float* weights, const float* params2, int t) {
    if ((t < 27) || (t >= 54 && t < 99)) {
        int b = (t < 27) ? t / 9 : 3 + (t - 54) / 9;
        int i = (t < 27) ? t % 9 : (t - 54) % 9;
        const float* pb_ = (b < 3) ? params + b * 36 : params2 + (b - 3) * 36;
        float bb = pb_[i * 4 + 1], zz = pb_[i * 4 + 2], xx = pb_[i * 4 + 3];
        mat2 M0 = mK0(bb), M1 = mK1(bb, zz, xx);
        mat2 U;
        if (i < 8) {
            U = mRY(pb_[(i + 1) * 4 + 0]);
        } else if (b == 2) {
            U = mRot(weights + 0);
        } else if (b == 7) {
            U = mI();
        } else {
            const float* nb = (b + 1 < 3) ? params + (b + 1) * 36
                                          : params2 + (b + 1 - 3) * 36;
            U = mRY(nb[0]);
        }
        M0 = mmul(U, M0); M1 = mmul(U, M1);
        float* o = fs + t * 48;
        if (i == 6 || i == 7) {
            // MODE 1 layout: [real M0: 8 floats][M1 full: 24 floats]
            o[0] = M0.m00.r; o[1] = M0.m00.r; o[2] = M0.m01.r; o[3] = M0.m01.r;
            o[4] = M0.m10.r; o[5] = M0.m10.r; o[6] = M0.m11.r; o[7] = M0.m11.r;
            wM(o + 8, M1);
        } else if (i == 8 && b != 2) {
            // MODE 2 layout: per tb (stride 16 floats): [Ar,Ar,Br,Br][c1 AB 12]
            for (int tb = 0; tb < 2; tb++) {
                float* o2 = o + tb * 16;
                float A = selA(M0, tb).r, Bc = selB(M0, tb).r;
                o2[0] = A; o2[1] = A; o2[2] = Bc; o2[3] = Bc;
                wAB(o2 + 4, selA(M1, tb), selB(M1, tb));
            }
        } else {
            expand(o, i, (i + 1) % 9, M0, M1);
        }
    } else if (t >= 27 && t < 54) {
        int L = (t - 27) / 9, i = (t - 27) % 9, r = L + 1;
        int tt = (i + r) % 9;
        mat2 R = mI(), Lt = mI();
        if (L == 0 && i < 8) R = mRot(weights + (0 * 9 + tt) * 3);
        if (L == 1 && i < 7) R = mRot(weights + (1 * 9 + tt) * 3);
        if (L == 2 && i < 6) R = mRot(weights + (2 * 9 + tt) * 3);
        if (L == 0 && i == 8) Lt = mRot(weights + (1 * 9 + 0) * 3);
        if (L == 1 && i == 7) Lt = mRot(weights + (2 * 9 + 0) * 3);
        if (L == 1 && i == 8) Lt = mRot(weights + (2 * 9 + 1) * 3);
        if (L == 2 && i == 6) Lt = mRY(params2[0]);
        mat2 M0 = mmul(Lt, R);
        mat2 M1 = mmul(Lt, mmul(mX(), R));
        expand(fs + t * 48, i, tt, M0, M1);
    } else if (t == 99) {
        mat2 M = mRot(weights + (1 * 9 + 1) * 3);
        float* o = fs + 99 * 48;
        wAB(o, selA(M, 0), selB(M, 0));
        wAB(o + 12, selA(M, 1), selB(M, 1));
    } else if (t == 100) {
        mat2 M = mRot(weights + (2 * 9 + 2) * 3);
        float* o = fs + 100 * 48;
        wAB(o, selA(M, 0), selB(M, 0));
        wAB(o + 12, selA(M, 1), selB(M, 1));
    } else if (t == 101) {
        float c, s; sincosf(0.5f * params[0], &s, &c);
        fs[RY0_F] = c; fs[RY0_F + 1] = s;
    }
}

// ------------------------------- sim kernel --------------------------------
#define TPB 96
__global__ void __launch_bounds__(TPB, 9)
sim_kernel(const float* __restrict__ adds,
           const float* __restrict__ params,
           const float* __restrict__ weights,
           const float* __restrict__ params2,
           float* __restrict__ out, int B) {
    __shared__ __align__(16) u64 shu[N_SLOTS * SLOT_U64 + 1];
    for (int t = threadIdx.x; t < 102; t += TPB)
        prep_slot((float*)shu, params, weights, params2, t);
    __syncthreads();
    const float* fs = (const float*)shu;

    int lane = threadIdx.x & 31;
    int item = blockIdx.x * (TPB >> 5) + (threadIdx.x >> 5);
    if (item >= B) return;

    // per-sample embedding angles
    float ec = 1.f, es = 0.f;
    if (lane < 9) {
        float a = adds[item * 9 + lane];
        sincosf(0.5f * a, &es, &ec);
    }
    float cw[9], sw[9];
#pragma unroll
    for (int w = 0; w < 9; w++) {
        cw[w] = __shfl_sync(0xffffffffu, ec, w);
        sw[w] = __shfl_sync(0xffffffffu, es, w);
    }

    // Tensor-product init (RY_0^{(0)} fused into wire-0 factor)
    float magl = ((lane & 8) ? sw[1] : cw[1]) * ((lane & 4) ? sw[2] : cw[2])
               * ((lane & 2) ? sw[3] : cw[3]) * ((lane & 1) ? sw[4] : cw[4]);
    int klane = __popc(lane & 15);
    bool b0 = (lane & 16) != 0;
    float ca0 = fs[RY0_F], sa0 = fs[RY0_F + 1];
    float v0r = b0 ? sa0 * cw[0] : ca0 * cw[0];
    float v0i = b0 ? -ca0 * sw[0] : sa0 * sw[0];

    float reA[16], imA[16];
    static_for<16>([&](auto rc) {
        constexpr int R = decltype(rc)::value;
        float mr = ((R & 8) ? sw[5] : cw[5]) * ((R & 4) ? sw[6] : cw[6])
                 * ((R & 2) ? sw[7] : cw[7]) * ((R & 1) ? sw[8] : cw[8]);
        float v = magl * mr;
        constexpr int KR = ((R >> 3) & 1) + ((R >> 2) & 1) + ((R >> 1) & 1) + (R & 1);
        int k = (klane + KR) & 3;
        reA[R] = (k == 0) ?  v * v0r : (k == 1) ?  v * v0i
               : (k == 2) ? -v * v0r :            -v * v0i;
        imA[R] = (k == 0) ?  v * v0i : (k == 1) ? -v * v0r
               : (k == 2) ? -v * v0i :             v * v0r;
    });
    u64 re[8], im[8];
    static_for<8>([&](auto qc) {
        constexpr int Q = decltype(qc)::value;
        re[Q] = pk2(reA[Q], reA[Q + 8]);
        im[Q] = pk2(imA[Q], imA[Q + 8]);
    });

#define SLOT(s) (shu + (s) * SLOT_U64)

    // QRAM blocks 0..2
    static_for<3>([&](auto bc) {
        constexpr int Bb = decltype(bc)::value;
        static_for<9>([&](auto ic) {
            constexpr int I = decltype(ic)::value;
            constexpr int MODE = (I == 6 || I == 7) ? 1
                               : (I == 8 ? ((Bb == 2) ? 0 : 2) : 0);
            gate<I, (I + 1) % 9, MODE>(re, im, SLOT(Bb * 9 + I), lane);
        });
    });

    // SEL L0
    static_for<9>([&](auto ic) {
        constexpr int I = decltype(ic)::value;
        gate<I, (I + 1) % 9>(re, im, SLOT(27 + I), lane);
    });
    g_1q<1>(re, im, SLOT(99), lane);
    // SEL L1
    static_for<9>([&](auto ic) {
        constexpr int I = decltype(ic)::value;
        gate<I, (I + 2) % 9>(re, im, SLOT(36 + I), lane);
    });
    g_1q<2>(re, im, SLOT(100), lane);
    // SEL L2
    static_for<9>([&](auto ic) {
        constexpr int I = decltype(ic)::value;
        gate<I, (I + 3) % 9>(re, im, SLOT(45 + I), lane);
    });

    // classifier blocks 3..7
    static_for<5>([&](auto bc) {
        constexpr int Bb = decltype(bc)::value;
        static_for<9>([&](auto ic) {
            constexpr int I = decltype(ic)::value;
            constexpr int MODE = (I == 6 || I == 7) ? 1 : (I == 8 ? 2 : 0);
            gate<I, (I + 1) % 9, MODE>(re, im, SLOT(54 + Bb * 9 + I), lane);
        });
    });

    // <Z0>: wire 0 = lane bit 4
    u64 acc2 = 0ull;
#pragma unroll
    for (int q = 0; q < 8; q++)
        acc2 = ffma2(re[q], re[q], ffma2(im[q], im[q], acc2));
    float lo, hi; upk2(acc2, lo, hi);
    float acc = lo + hi;
    if (lane & 16) acc = -acc;
#pragma unroll
    for (int m = 16; m >= 1; m >>= 1) acc += __shfl_xor_sync(0xffffffffu, acc, m);
    if (lane == 0) out[item] = acc;
}

// ------------------------------ launcher -----------------------------------
extern "C" void kernel_launch(void* const* d_in, const int* in_sizes, int n_in,
                              void* d_out, int out_size) {
    const float* adds    = (const float*)d_in[0];
    const float* params  = (const float*)d_in[1];
    const float* weights = (const float*)d_in[2];
    const float* params2 = (const float*)d_in[3];
    float* out = (float*)d_out;

    int B = in_sizes[0] / 9;

    int warpsPerBlock = TPB / 32;
    int blocks = (B + warpsPerBlock - 1) / warpsPerBlock;
    sim_kernel<<<blocks, TPB>>>(adds, params, weights, params2, out, B);
}

// round 17
// speedup vs baseline: 1.1573x; 1.1573x over previous
#include <cuda_runtime.h>
#include <cuda_bf16.h>

// ---------------------------------------------------------------------------
// 9-wire statevector simulator. One warp per batch item, 16 complex amps/lane.
// SoA f32x2 packing: u64 re[8]/im[8] hold (component of amp q, amp q+8),
// pairing along reg bit 3 (= wire 5).
//
// R14: TPB back to 128 (R12 proven config: one prep slot/thread, 2048 blocks),
// keeping R13's real-M0 specialized gate paths (MODE 1/2).
//
// Amplitude index idx[8:0]: wire w <-> bit (8-w).
//   wires 0..4 -> lane bits 4..0 (shuffles)
//   wire  5    -> f32x2 packed half
//   wires 6..8 -> reg bits 2..0 of q
// ---------------------------------------------------------------------------

using u64 = unsigned long long;

#define N_SLOTS   101                  // 99 fused gates + 2 standalone Rots
#define SLOT_U64  24                   // 192 bytes per gate slot
#define RY0_F     (N_SLOTS * SLOT_U64 * 2)   // float index of (ca,sa)

template<int V> struct IC { static constexpr int value = V; };
template<int N, typename F>
__device__ __forceinline__ void static_for(F&& f) {
    if constexpr (N > 0) { static_for<N - 1>(f); f(IC<N - 1>{}); }
}

// ------------------------- packed f32x2 helpers ----------------------------
__device__ __forceinline__ u64 pk2(float lo, float hi) {
    u64 r;
    asm("mov.b64 %0, {%1, %2};" : "=l"(r)
        : "r"(__float_as_uint(lo)), "r"(__float_as_uint(hi)));
    return r;
}
__device__ __forceinline__ void upk2(u64 a, float& lo, float& hi) {
    unsigned l_, h_;
    asm("mov.b64 {%0, %1}, %2;" : "=r"(l_), "=r"(h_) : "l"(a));
    lo = __uint_as_float(l_); hi = __uint_as_float(h_);
}
__device__ __forceinline__ u64 swp(u64 a) {
    float x, y; upk2(a, x, y); return pk2(y, x);
}
__device__ __forceinline__ u64 ffma2(u64 a, u64 b, u64 c) {
    u64 d; asm("fma.rn.f32x2 %0, %1, %2, %3;" : "=l"(d) : "l"(a), "l"(b), "l"(c));
    return d;
}
__device__ __forceinline__ u64 fmul2(u64 a, u64 b) {
    u64 d; asm("mul.rn.f32x2 %0, %1, %2;" : "=l"(d) : "l"(a), "l"(b));
    return d;
}
__device__ __forceinline__ u64 shx(u64 v, int m) { return __shfl_xor_sync(0xffffffffu, v, m); }

// --------------------- coefficient bundles (loaded from smem) --------------
// AB record (6 u64): Ar,Ai,nAi,Br,Bi,nBi  — out = A*self + B*partner
struct CoefAB { u64 Ar, Ai, nAi, Br, Bi, nBi; };
__device__ __forceinline__ CoefAB ldAB(const u64* r) {
    return { r[0], r[1], r[2], r[3], r[4], r[5] };
}
__device__ __forceinline__ void apply_AB(u64& re, u64& im, u64 pre, u64 pim, const CoefAB& c) {
    u64 nre = ffma2(c.Br, pre, ffma2(c.nBi, pim, ffma2(c.nAi, im, fmul2(c.Ar, re))));
    u64 nim = ffma2(c.Bi, pre, ffma2(c.Br, pim, ffma2(c.Ai, re, fmul2(c.Ar, im))));
    re = nre; im = nim;
}
// PQ (target = packed wire 5): same six-slot record
__device__ __forceinline__ void apply_PQ(u64& re, u64& im, const CoefAB& c) {
    u64 sre = swp(re), sim = swp(im);
    u64 nre = ffma2(c.Br, sre, ffma2(c.nBi, sim, ffma2(c.nAi, im, fmul2(c.Ar, re))));
    u64 nim = ffma2(c.Bi, sre, ffma2(c.Br, sim, ffma2(c.Ai, re, fmul2(c.Ar, im))));
    re = nre; im = nim;
}
// Full 2x2 record (12 u64)
struct CoefM { u64 r00, i00, n00, r01, i01, n01, r10, i10, n10, r11, i11, n11; };
__device__ __forceinline__ CoefM ldM(const u64* r) {
    return { r[0], r[1], r[2], r[3], r[4], r[5], r[6], r[7], r[8], r[9], r[10], r[11] };
}
__device__ __forceinline__ void apply_pair(u64& req, u64& imq, u64& rep, u64& imp, const CoefM& c) {
    u64 nreq = ffma2(c.r01, rep, ffma2(c.n01, imp, ffma2(c.n00, imq, fmul2(c.r00, req))));
    u64 nimq = ffma2(c.i01, rep, ffma2(c.r01, imp, ffma2(c.i00, req, fmul2(c.r00, imq))));
    u64 nrep = ffma2(c.r11, rep, ffma2(c.n11, imp, ffma2(c.n10, imq, fmul2(c.r10, req))));
    u64 nimp = ffma2(c.i11, rep, ffma2(c.r11, imp, ffma2(c.i10, req, fmul2(c.r10, imq))));
    req = nreq; imq = nimq; rep = nrep; imp = nimp;
}

// ------------------------------ gate ---------------------------------------
// MODE 0: generic layouts.
// MODE 1: C in {6,7}, T=C+1 (both reg), M0 REAL: [4 u64 realM0][12 u64 M1]
// MODE 2: C=8 (reg), T=0 (lane), M0 REAL: per tb (stride 8 u64):
//         [Ar,Br real: 2 u64][c1 AB: 6 u64]
template<int C, int T, int MODE = 0>
__device__ __forceinline__ void gate(u64 (&re)[8], u64 (&im)[8], const u64* g, int lane) {
    if constexpr (T < 5) {
        constexpr int LMT = 1 << (4 - T);
        int tb = (lane >> (4 - T)) & 1;
        if constexpr (C < 5) {
            int cb = (lane >> (4 - C)) & 1;
            CoefAB c = ldAB(g + (cb * 2 + tb) * 6);
#pragma unroll
            for (int q = 0; q < 8; q++) {
                u64 pre = shx(re[q], LMT), pim = shx(im[q], LMT);
                apply_AB(re[q], im[q], pre, pim, c);
            }
        } else if constexpr (MODE == 2) {   // C==8, real M0
            const u64* r = g + tb * 8;
            u64 A0 = r[0], B0 = r[1];
            CoefAB c1 = ldAB(r + 2);
#pragma unroll
            for (int q = 0; q < 8; q++) {
                u64 pre = shx(re[q], LMT), pim = shx(im[q], LMT);
                if (q & 1) {
                    apply_AB(re[q], im[q], pre, pim, c1);
                } else {
                    re[q] = ffma2(B0, pre, fmul2(A0, re[q]));
                    im[q] = ffma2(B0, pim, fmul2(A0, im[q]));
                }
            }
        } else {   // generic C >= 6
            constexpr int MC = 1 << (8 - C);
            const u64* r = g + tb * 12;
            CoefAB c0 = ldAB(r), c1 = ldAB(r + 6);
#pragma unroll
            for (int q = 0; q < 8; q++) {
                u64 pre = shx(re[q], LMT), pim = shx(im[q], LMT);
                apply_AB(re[q], im[q], pre, pim, (q & MC) ? c1 : c0);
            }
        }
    } else if constexpr (T == 5) {      // control always a lane wire here
        int cb = (lane >> (4 - C)) & 1;
        CoefAB c = ldAB(g + cb * 6);
#pragma unroll
        for (int q = 0; q < 8; q++) apply_PQ(re[q], im[q], c);
    } else {
        constexpr int MT = 1 << (8 - T);
        if constexpr (C < 5) {
            int cb = (lane >> (4 - C)) & 1;
            CoefM c = ldM(g + cb * 12);
#pragma unroll
            for (int q = 0; q < 8; q++) if (!(q & MT))
                apply_pair(re[q], im[q], re[q | MT], im[q | MT], c);
        } else if constexpr (C == 5) {
            CoefM c = ldM(g);
#pragma unroll
            for (int q = 0; q < 8; q++) if (!(q & MT))
                apply_pair(re[q], im[q], re[q | MT], im[q | MT], c);
        } else if constexpr (MODE == 1) {   // both reg, real M0
            constexpr int MC = 1 << (8 - C);
            {
                u64 q00 = g[0], q01 = g[1], q10 = g[2], q11 = g[3];
#pragma unroll
                for (int q = 0; q < 8; q++) if (!(q & MT) && !(q & MC)) {
                    u64 ar = re[q], br = re[q | MT], ai = im[q], bi = im[q | MT];
                    re[q]      = ffma2(q01, br, fmul2(q00, ar));
                    im[q]      = ffma2(q01, bi, fmul2(q00, ai));
                    re[q | MT] = ffma2(q11, br, fmul2(q10, ar));
                    im[q | MT] = ffma2(q11, bi, fmul2(q10, ai));
                }
            }
            {
                CoefM c = ldM(g + 4);
#pragma unroll
                for (int q = 0; q < 8; q++) if (!(q & MT) && (q & MC))
                    apply_pair(re[q], im[q], re[q | MT], im[q | MT], c);
            }
        } else {
            constexpr int MC = 1 << (8 - C);
            {
                CoefM c = ldM(g);
#pragma unroll
                for (int q = 0; q < 8; q++) if (!(q & MT) && !(q & MC))
                    apply_pair(re[q], im[q], re[q | MT], im[q | MT], c);
            }
            {
                CoefM c = ldM(g + 12);
#pragma unroll
                for (int q = 0; q < 8; q++) if (!(q & MT) && (q & MC))
                    apply_pair(re[q], im[q], re[q | MT], im[q | MT], c);
            }
        }
    }
}

// Standalone 1q on lane wire W: 2 AB records indexed by tbit
template<int W>
__device__ __forceinline__ void g_1q(u64 (&re)[8], u64 (&im)[8], const u64* g, int lane) {
    constexpr int LMT = 1 << (4 - W);
    int tb = (lane >> (4 - W)) & 1;
    CoefAB c = ldAB(g + tb * 6);
#pragma unroll
    for (int q = 0; q < 8; q++) {
        u64 pre = shx(re[q], LMT), pim = shx(im[q], LMT);
        apply_AB(re[q], im[q], pre, pim, c);
    }
}

// ------------------------- prep: complex 2x2 algebra -----------------------
struct cpx { float r, i; };
__device__ __forceinline__ cpx cmulh(cpx x, cpx y) {
    return { x.r * y.r - x.i * y.i, x.r * y.i + x.i * y.r };
}
__device__ __forceinline__ cpx caddh(cpx x, cpx y) { return { x.r + y.r, x.i + y.i }; }
struct mat2 { cpx m00, m01, m10, m11; };
__device__ mat2 mmul(mat2 A, mat2 B) {
    return { caddh(cmulh(A.m00, B.m00), cmulh(A.m01, B.m10)),
             caddh(cmulh(A.m00, B.m01), cmulh(A.m01, B.m11)),
             caddh(cmulh(A.m10, B.m00), cmulh(A.m11, B.m10)),
             caddh(cmulh(A.m10, B.m01), cmulh(A.m11, B.m11)) };
}
__device__ mat2 mI() { return { {1,0},{0,0},{0,0},{1,0} }; }
__device__ mat2 mX() { return { {0,0},{1,0},{1,0},{0,0} }; }
__device__ mat2 mRY(float t) {
    float c, s; sincosf(0.5f * t, &s, &c);
    return { {c,0},{-s,0},{s,0},{c,0} };
}
__device__ mat2 mRot(const float* w) {
    float phi = w[0], th = w[1], om = w[2];
    float ct, st; sincosf(0.5f * th, &st, &ct);
    float ca, sa; sincosf(0.5f * (phi + om), &sa, &ca);
    float cb, sb; sincosf(0.5f * (phi - om), &sb, &cb);
    return { { ct * ca, -ct * sa }, { -st * cb, -st * sb },
             { st * cb, -st * sb }, { ct * ca,  ct * sa } };
}
__device__ mat2 mK0(float pb) {
    float cb, sb; sincosf(0.5f * pb, &sb, &cb);
    return { {sb,0},{cb,0},{cb,0},{-sb,0} };
}
__device__ mat2 mK1(float pb, float pz, float px) {
    float cb, sb; sincosf(0.5f * pb, &sb, &cb);
    float cz, sz; sincosf(0.5f * pz, &sz, &cz);
    float cx, sx; sincosf(0.5f * px, &sx, &cx);
    float d00r =  cz * cb, d00i =  sz * cb;
    float d01r = -cz * sb, d01i = -sz * sb;
    float d10r =  cz * sb, d10i = -sz * sb;
    float d11r =  cz * cb, d11i = -sz * cb;
    mat2 W;
    W.m00 = {  cx * d00r + sx * d10i,  cx * d00i - sx * d10r };
    W.m01 = {  cx * d01r + sx * d11i,  cx * d01i - sx * d11r };
    W.m10 = {  sx * d00i + cx * d10r, -sx * d00r + cx * d10i };
    W.m11 = {  sx * d01i + cx * d11r, -sx * d01r + cx * d11i };
    return W;
}

// ---- record writers (float offsets) ----
__device__ __forceinline__ cpx selA(const mat2& M, int tb) { return tb ? M.m11 : M.m00; }
__device__ __forceinline__ cpx selB(const mat2& M, int tb) { return tb ? M.m10 : M.m01; }
__device__ void wAB(float* o, cpx A, cpx B) {
    o[0] = A.r; o[1] = A.r; o[2] = A.i; o[3] = A.i; o[4] = -A.i; o[5] = -A.i;
    o[6] = B.r; o[7] = B.r; o[8] = B.i; o[9] = B.i; o[10] = -B.i; o[11] = -B.i;
}
__device__ void wM(float* o, mat2 M) {
    cpx v[4] = { M.m00, M.m01, M.m10, M.m11 };
    for (int k = 0; k < 4; k++) {
        o[k*6+0] = v[k].r; o[k*6+1] = v[k].r;
        o[k*6+2] = v[k].i; o[k*6+3] = v[k].i;
        o[k*6+4] = -v[k].i; o[k*6+5] = -v[k].i;
    }
}
__device__ void wMmix(float* o, mat2 A, mat2 B) {   // halves (A=ctrl0, B=ctrl1) on wire5
    cpx va[4] = { A.m00, A.m01, A.m10, A.m11 };
    cpx vb[4] = { B.m00, B.m01, B.m10, B.m11 };
    for (int k = 0; k < 4; k++) {
        o[k*6+0] = va[k].r; o[k*6+1] = vb[k].r;
        o[k*6+2] = va[k].i; o[k*6+3] = vb[k].i;
        o[k*6+4] = -va[k].i; o[k*6+5] = -vb[k].i;
    }
}
__device__ void wPQ(float* o, mat2 M) {   // P=(m00,m11) diag halves, Q=(m01,m10)
    o[0] = M.m00.r; o[1] = M.m11.r; o[2] = M.m00.i; o[3] = M.m11.i;
    o[4] = -M.m00.i; o[5] = -M.m11.i;
    o[6] = M.m01.r; o[7] = M.m10.r; o[8] = M.m01.i; o[9] = M.m10.i;
    o[10] = -M.m01.i; o[11] = -M.m10.i;
}

// expand gate (C,T) with blocks M0,M1 into slot table (generic layouts)
__device__ void expand(float* o, int C, int T, mat2 M0, mat2 M1) {
    if (T < 5 && C < 5) {
        for (int cb = 0; cb < 2; cb++) for (int tb = 0; tb < 2; tb++) {
            mat2& M = cb ? M1 : M0;
            wAB(o + (cb * 2 + tb) * 12, selA(M, tb), selB(M, tb));
        }
    } else if (T < 5) {                    // C >= 6
        for (int tb = 0; tb < 2; tb++) {
            wAB(o + tb * 24,      selA(M0, tb), selB(M0, tb));
            wAB(o + tb * 24 + 12, selA(M1, tb), selB(M1, tb));
        }
    } else if (T == 5) {                   // C < 5 always
        wPQ(o, M0); wPQ(o + 12, M1);
    } else if (C == 5) {
        wMmix(o, M0, M1);
    } else {                               // [M0 | M1] records
        wM(o, M0); wM(o + 24, M1);
    }
}

// in-block prep: fusion logic + per-lane expansion (incl. real-M0 layouts)
__device__ void prep_slot(float* fs, const float* params,
                          const float* weights, const float* params2, int t) {
    if ((t < 27) || (t >= 54 && t < 99)) {
        int b = (t < 27) ? t / 9 : 3 + (t - 54) / 9;
        int i = (t < 27) ? t % 9 : (t - 54) % 9;
        const float* pb_ = (b < 3) ? params + b * 36 : params2 + (b - 3) * 36;
        float bb = pb_[i * 4 + 1], zz = pb_[i * 4 + 2], xx = pb_[i * 4 + 3];
        mat2 M0 = mK0(bb), M1 = mK1(bb, zz, xx);
        mat2 U;
        if (i < 8) {
            U = mRY(pb_[(i + 1) * 4 + 0]);
        } else if (b == 2) {
            U = mRot(weights + 0);
        } else if (b == 7) {
            U = mI();
        } else {
            const float* nb = (b + 1 < 3) ? params + (b + 1) * 36
                                          : params2 + (b + 1 - 3) * 36;
            U = mRY(nb[0]);
        }
        M0 = mmul(U, M0); M1 = mmul(U, M1);
        float* o = fs + t * 48;
        if (i == 6 || i == 7) {
            // MODE 1 layout: [real M0: 8 floats][M1 full: 24 floats]
            o[0] = M0.m00.r; o[1] = M0.m00.r; o[2] = M0.m01.r; o[3] = M0.m01.r;
            o[4] = M0.m10.r; o[5] = M0.m10.r; o[6] = M0.m11.r; o[7] = M0.m11.r;
            wM(o + 8, M1);
        } else if (i == 8 && b != 2) {
            // MODE 2 layout: per tb (stride 16 floats): [Ar,Ar,Br,Br][c1 AB 12]
            for (int tb = 0; tb < 2; tb++) {
                float* o2 = o + tb * 16;
                float A = selA(M0, tb).r, Bc = selB(M0, tb).r;
                o2[0] = A; o2[1] = A; o2[2] = Bc; o2[3] = Bc;
                wAB(o2 + 4, selA(M1, tb), selB(M1, tb));
            }
        } else {
            expand(o, i, (i + 1) % 9, M0, M1);
        }
    } else if (t >= 27 && t < 54) {
        int L = (t - 27) / 9, i = (t - 27) % 9, r = L + 1;
        int tt = (i + r) % 9;
        mat2 R = mI(), Lt = mI();
        if (L == 0 && i < 8) R = mRot(weights + (0 * 9 + tt) * 3);
        if (L == 1 && i < 7) R = mRot(weights + (1 * 9 + tt) * 3);
        if (L == 2 && i < 6) R = mRot(weights + (2 * 9 + tt) * 3);
        if (L == 0 && i == 8) Lt = mRot(weights + (1 * 9 + 0) * 3);
        if (L == 1 && i == 7) Lt = mRot(weights + (2 * 9 + 0) * 3);
        if (L == 1 && i == 8) Lt = mRot(weights + (2 * 9 + 1) * 3);
        if (L == 2 && i == 6) Lt = mRY(params2[0]);
        mat2 M0 = mmul(Lt, R);
        mat2 M1 = mmul(Lt, mmul(mX(), R));
        expand(fs + t * 48, i, tt, M0, M1);
    } else if (t == 99) {
        mat2 M = mRot(weights + (1 * 9 + 1) * 3);
        float* o = fs + 99 * 48;
        wAB(o, selA(M, 0), selB(M, 0));
        wAB(o + 12, selA(M, 1), selB(M, 1));
    } else if (t == 100) {
        mat2 M = mRot(weights + (2 * 9 + 2) * 3);
        float* o = fs + 100 * 48;
        wAB(o, selA(M, 0), selB(M, 0));
        wAB(o + 12, selA(M, 1), selB(M, 1));
    } else if (t == 101) {
        float c, s; sincosf(0.5f * params[0], &s, &c);
        fs[RY0_F] = c; fs[RY0_F + 1] = s;
    }
}

// ------------------------------- sim kernel --------------------------------
#define TPB 128
__global__ void __launch_bounds__(TPB, 7)
sim_kernel(const float* __restrict__ adds,
           const float* __restrict__ params,
           const float* __restrict__ weights,
           const float* __restrict__ params2,
           float* __restrict__ out, int B) {
    __shared__ __align__(16) u64 shu[N_SLOTS * SLOT_U64 + 1];
    prep_slot((float*)shu, params, weights, params2, threadIdx.x);
    __syncthreads();
    const float* fs = (const float*)shu;

    int lane = threadIdx.x & 31;
    int item = blockIdx.x * (TPB >> 5) + (threadIdx.x >> 5);
    if (item >= B) return;

    // per-sample embedding angles
    float ec = 1.f, es = 0.f;
    if (lane < 9) {
        float a = adds[item * 9 + lane];
        sincosf(0.5f * a, &es, &ec);
    }
    float cw[9], sw[9];
#pragma unroll
    for (int w = 0; w < 9; w++) {
        cw[w] = __shfl_sync(0xffffffffu, ec, w);
        sw[w] = __shfl_sync(0xffffffffu, es, w);
    }

    // Tensor-product init (RY_0^{(0)} fused into wire-0 factor)
    float magl = ((lane & 8) ? sw[1] : cw[1]) * ((lane & 4) ? sw[2] : cw[2])
               * ((lane & 2) ? sw[3] : cw[3]) * ((lane & 1) ? sw[4] : cw[4]);
    int klane = __popc(lane & 15);
    bool b0 = (lane & 16) != 0;
    float ca0 = fs[RY0_F], sa0 = fs[RY0_F + 1];
    float v0r = b0 ? sa0 * cw[0] : ca0 * cw[0];
    float v0i = b0 ? -ca0 * sw[0] : sa0 * sw[0];

    float reA[16], imA[16];
    static_for<16>([&](auto rc) {
        constexpr int R = decltype(rc)::value;
        float mr = ((R & 8) ? sw[5] : cw[5]) * ((R & 4) ? sw[6] : cw[6])
                 * ((R & 2) ? sw[7] : cw[7]) * ((R & 1) ? sw[8] : cw[8]);
        float v = magl * mr;
        constexpr int KR = ((R >> 3) & 1) + ((R >> 2) & 1) + ((R >> 1) & 1) + (R & 1);
        int k = (klane + KR) & 3;
        reA[R] = (k == 0) ?  v * v0r : (k == 1) ?  v * v0i
               : (k == 2) ? -v * v0r :            -v * v0i;
        imA[R] = (k == 0) ?  v * v0i : (k == 1) ? -v * v0r
               : (k == 2) ? -v * v0i :             v * v0r;
    });
    u64 re[8], im[8];
    static_for<8>([&](auto qc) {
        constexpr int Q = decltype(qc)::value;
        re[Q] = pk2(reA[Q], reA[Q + 8]);
        im[Q] = pk2(imA[Q], imA[Q + 8]);
    });

#define SLOT(s) (shu + (s) * SLOT_U64)

    // QRAM blocks 0..2
    static_for<3>([&](auto bc) {
        constexpr int Bb = decltype(bc)::value;
        static_for<9>([&](auto ic) {
            constexpr int I = decltype(ic)::value;
            constexpr int MODE = (I == 6 || I == 7) ? 1
                               : (I == 8 ? ((Bb == 2) ? 0 : 2) : 0);
            gate<I, (I + 1) % 9, MODE>(re, im, SLOT(Bb * 9 + I), lane);
        });
    });

    // SEL L0
    static_for<9>([&](auto ic) {
        constexpr int I = decltype(ic)::value;
        gate<I, (I + 1) % 9>(re, im, SLOT(27 + I), lane);
    });
    g_1q<1>(re, im, SLOT(99), lane);
    // SEL L1
    static_for<9>([&](auto ic) {
        constexpr int I = decltype(ic)::value;
        gate<I, (I + 2) % 9>(re, im, SLOT(36 + I), lane);
    });
    g_1q<2>(re, im, SLOT(100), lane);
    // SEL L2
    static_for<9>([&](auto ic) {
        constexpr int I = decltype(ic)::value;
        gate<I, (I + 3) % 9>(re, im, SLOT(45 + I), lane);
    });

    // classifier blocks 3..7
    static_for<5>([&](auto bc) {
        constexpr int Bb = decltype(bc)::value;
        static_for<9>([&](auto ic) {
            constexpr int I = decltype(ic)::value;
            constexpr int MODE = (I == 6 || I == 7) ? 1 : (I == 8 ? 2 : 0);
            gate<I, (I + 1) % 9, MODE>(re, im, SLOT(54 + Bb * 9 + I), lane);
        });
    });

    // <Z0>: wire 0 = lane bit 4
    u64 acc2 = 0ull;
#pragma unroll
    for (int q = 0; q < 8; q++)
        acc2 = ffma2(re[q], re[q], ffma2(im[q], im[q], acc2));
    float lo, hi; upk2(acc2, lo, hi);
    float acc = lo + hi;
    if (lane & 16) acc = -acc;
#pragma unroll
    for (int m = 16; m >= 1; m >>= 1) acc += __shfl_xor_sync(0xffffffffu, acc, m);
    if (lane == 0) out[item] = acc;
}

// ------------------------------ launcher -----------------------------------
extern "C" void kernel_launch(void* const* d_in, const int* in_sizes, int n_in,
                              void* d_out, int out_size) {
    const float* adds    = (const float*)d_in[0];
    const float* params  = (const float*)d_in[1];
    const float* weights = (const float*)d_in[2];
    const float* params2 = (const float*)d_in[3];
    float* out = (float*)d_out;

    int B = in_sizes[0] / 9;

    int warpsPerBlock = TPB / 32;
    int blocks = (B + warpsPerBlock - 1) / warpsPerBlock;
    sim_kernel<<<blocks, TPB>>>(adds, params, weights, params2, out, B);
}